// round 7
// baseline (speedup 1.0000x reference)
#include <cuda_runtime.h>
#include <math.h>

#define FDIM 256
#define H 128
#define NMAX 50000
#define EMAX 1600000

// Scratch (allocation-free rule: __device__ globals)
#define BUF0_OFF 0
#define BUF1_OFF (NMAX * H)
#define BUF2_OFF (2 * NMAX * H)
__device__ float g_scratch[3 * NMAX * H];
__device__ float g_dis[NMAX];
__device__ int   g_cnt[NMAX];
__device__ int   g_fill[NMAX];
__device__ int   g_rowptr[NMAX + 1];
__device__ int   g_csr_src[EMAX];
__device__ float g_csr_norm[EMAX];
__device__ int   g_blocksum[64];
__device__ int   g_blockoff[64];

__device__ __forceinline__ const float* rsv(const float* p, int off) {
    return p ? p : (g_scratch + off);
}

// ---------------------------------------------------------------------------
// CSR build: count -> dis -> 3-phase scan -> fill
// ---------------------------------------------------------------------------
__global__ void zero_int_kernel(int n) {
    int i = blockIdx.x * blockDim.x + threadIdx.x;
    if (i < n) { g_cnt[i] = 0; g_fill[i] = 0; }
}

__global__ void count_kernel(const int* __restrict__ ei, int E) {
    int e = blockIdx.x * blockDim.x + threadIdx.x;
    if (e < E) atomicAdd(&g_cnt[ei[(size_t)E + e]], 1);
}

__global__ void dis_kernel(int n) {
    int i = blockIdx.x * blockDim.x + threadIdx.x;
    if (i < n) g_dis[i] = rsqrtf((float)(g_cnt[i] + 1));  // +1 self loop
}

__global__ void scan_phase1(int n) {
    int t = threadIdx.x;
    int base = blockIdx.x * 1024 + t * 4;
    int s = 0;
#pragma unroll
    for (int j = 0; j < 4; j++) { int i = base + j; if (i < n) s += g_cnt[i]; }
#pragma unroll
    for (int off = 16; off; off >>= 1) s += __shfl_xor_sync(0xffffffffu, s, off);
    __shared__ int wsum[8];
    if ((t & 31) == 0) wsum[t >> 5] = s;
    __syncthreads();
    if (t == 0) {
        int tot = 0;
#pragma unroll
        for (int w = 0; w < 8; w++) tot += wsum[w];
        g_blocksum[blockIdx.x] = tot;
    }
}

__global__ void scan_phase2(int nb) {
    __shared__ int sh[64];
    int t = threadIdx.x;
    int v = (t < nb) ? g_blocksum[t] : 0;
    sh[t] = v;
    __syncthreads();
    for (int off = 1; off < 64; off <<= 1) {
        int tmp = (t >= off) ? sh[t - off] : 0;
        __syncthreads();
        sh[t] += tmp;
        __syncthreads();
    }
    if (t < nb) g_blockoff[t] = sh[t] - v;  // exclusive
}

__global__ void scan_phase3(int n, int E) {
    int t = threadIdx.x;
    int base = blockIdx.x * 1024 + t * 4;
    int v[4]; int s = 0;
#pragma unroll
    for (int j = 0; j < 4; j++) { int i = base + j; v[j] = (i < n) ? g_cnt[i] : 0; s += v[j]; }
    int incl = s;
#pragma unroll
    for (int off = 1; off < 32; off <<= 1) {
        int tmp = __shfl_up_sync(0xffffffffu, incl, off);
        if ((t & 31) >= off) incl += tmp;
    }
    __shared__ int wtot[8];
    __shared__ int woff[8];
    if ((t & 31) == 31) wtot[t >> 5] = incl;
    __syncthreads();
    if (t < 8) {
        int wv = wtot[t];
        int wincl = wv;
#pragma unroll
        for (int off = 1; off < 8; off <<= 1) {
            int tmp = __shfl_up_sync(0x000000ffu, wincl, off);
            if (t >= off) wincl += tmp;
        }
        woff[t] = wincl - wv;
    }
    __syncthreads();
    int prefix = g_blockoff[blockIdx.x] + woff[t >> 5] + (incl - s);
#pragma unroll
    for (int j = 0; j < 4; j++) {
        int i = base + j;
        if (i < n) g_rowptr[i] = prefix;
        prefix += v[j];
    }
    if (blockIdx.x == 0 && t == 0) g_rowptr[n] = E;
}

__global__ void fill_kernel(const int* __restrict__ ei, int E) {
    int e = blockIdx.x * blockDim.x + threadIdx.x;
    if (e >= E) return;
    int s = ei[e];
    int d = ei[(size_t)E + e];
    int pos = g_rowptr[d] + atomicAdd(&g_fill[d], 1);
    g_csr_src[pos] = s;
    g_csr_norm[pos] = g_dis[s] * g_dis[d];
}

// ---------------------------------------------------------------------------
// TF32 tensor-core GEMM, N fixed to 128.
// C[M,128] = op_in(A[M,K]) @ W[K,128] (+bias) (relu?)
// Block tile 128x128, BK=32, 256 threads (8 warps, 2x4), warp tile 64x32.
// Operands staged in mma-fragment-native smem layout (scatter at STS).
// ---------------------------------------------------------------------------
__device__ __forceinline__ unsigned f2tf32(float f) {
    unsigned r;
    asm("cvt.rna.tf32.f32 %0, %1;" : "=r"(r) : "f"(f));
    return r;
}

template <bool RIN, bool ROUT, bool BIAS>
__global__ __launch_bounds__(256)
void gemm_tf32(const float* __restrict__ Aext, int aOff,
               const float* __restrict__ W,
               const float* __restrict__ bias,
               int cOff, int M, int K) {
    const float* A = rsv(Aext, aOff);
    float* C = g_scratch + cOff;

    // fragment-layout smem: A 128x32 (32 blocks of 32thr x 4reg),
    //                       B 32x128 (64 blocks of 32thr x 2reg)
    __shared__ unsigned sA[4096];
    __shared__ unsigned sB[4096];

    const int tid = threadIdx.x;
    const int lane = tid & 31;
    const int wid = tid >> 5;
    const int warp_m = wid >> 2;   // 0..1 (64 rows each)
    const int warp_n = wid & 3;    // 0..3 (32 cols each)
    const int g = lane >> 2;       // 0..7
    const int tig = lane & 3;      // 0..3
    const int rowBase = blockIdx.x * 128;

    float acc[4][4][4];
#pragma unroll
    for (int mt = 0; mt < 4; mt++)
#pragma unroll
        for (int nt = 0; nt < 4; nt++)
#pragma unroll
            for (int r = 0; r < 4; r++) acc[mt][nt][r] = 0.0f;

    for (int k0 = 0; k0 < K; k0 += 32) {
        // ---- stage A tile (128 x 32) into fragment layout ----
#pragma unroll
        for (int it = 0; it < 4; it++) {
            int fidx = it * 256 + tid;       // 1024 float4 slots
            int row = fidx >> 3;             // 0..127
            int col4 = fidx & 7;             // 0..7 (float4 within 32 cols)
            int grow = rowBase + row;
            float4 v = make_float4(0.f, 0.f, 0.f, 0.f);
            if (grow < M) v = *(const float4*)(A + (size_t)grow * K + k0 + col4 * 4);
            if (RIN) {
                v.x = fmaxf(v.x, 0.f); v.y = fmaxf(v.y, 0.f);
                v.z = fmaxf(v.z, 0.f); v.w = fmaxf(v.w, 0.f);
            }
            int mt = row >> 4, rr = row & 15;
            int gg = rr & 7, ib0 = rr >> 3;
#pragma unroll
            for (int j = 0; j < 4; j++) {
                int col = col4 * 4 + j;
                int ksub = col >> 3, kk = col & 7;
                int tg = kk & 3, ib1 = kk >> 2;
                sA[((mt * 4 + ksub) * 32 + gg * 4 + tg) * 4 + ib0 + 2 * ib1] =
                    f2tf32((&v.x)[j]);
            }
        }
        // ---- stage B tile (32 x 128) into fragment layout ----
#pragma unroll
        for (int it = 0; it < 4; it++) {
            int fidx = it * 256 + tid;       // 1024 float4 slots
            int krow = fidx >> 5;            // 0..31
            int col4 = fidx & 31;            // 0..31
            float4 v = *(const float4*)(W + (size_t)(k0 + krow) * 128 + col4 * 4);
            int ksub = krow >> 3, kk = krow & 7;
            int tg = kk & 3, jreg = kk >> 2;
#pragma unroll
            for (int j = 0; j < 4; j++) {
                int col = col4 * 4 + j;
                int nt = col >> 3, gg = col & 7;
                sB[((nt * 4 + ksub) * 32 + gg * 4 + tg) * 2 + jreg] =
                    f2tf32((&v.x)[j]);
            }
        }
        __syncthreads();

        // ---- compute: 4 k-subtiles of 8 ----
#pragma unroll
        for (int ksub = 0; ksub < 4; ksub++) {
            uint4 af[4];
            uint2 bf[4];
#pragma unroll
            for (int mt = 0; mt < 4; mt++)
                af[mt] = ((const uint4*)sA)[((warp_m * 4 + mt) * 4 + ksub) * 32 + lane];
#pragma unroll
            for (int nt = 0; nt < 4; nt++)
                bf[nt] = ((const uint2*)sB)[((warp_n * 4 + nt) * 4 + ksub) * 32 + lane];
#pragma unroll
            for (int mt = 0; mt < 4; mt++)
#pragma unroll
                for (int nt = 0; nt < 4; nt++) {
                    asm volatile(
                        "mma.sync.aligned.m16n8k8.row.col.f32.tf32.tf32.f32 "
                        "{%0,%1,%2,%3}, {%4,%5,%6,%7}, {%8,%9}, {%0,%1,%2,%3};\n"
                        : "+f"(acc[mt][nt][0]), "+f"(acc[mt][nt][1]),
                          "+f"(acc[mt][nt][2]), "+f"(acc[mt][nt][3])
                        : "r"(af[mt].x), "r"(af[mt].y), "r"(af[mt].z), "r"(af[mt].w),
                          "r"(bf[nt].x), "r"(bf[nt].y));
                }
        }
        __syncthreads();
    }

    // ---- epilogue ----
#pragma unroll
    for (int mt = 0; mt < 4; mt++) {
        int row0 = rowBase + warp_m * 64 + mt * 16 + g;
#pragma unroll
        for (int nt = 0; nt < 4; nt++) {
            int col = warp_n * 32 + nt * 8 + tig * 2;
            float b0 = 0.f, b1 = 0.f;
            if (BIAS) { b0 = bias[col]; b1 = bias[col + 1]; }
            float2 v01, v23;
            v01.x = acc[mt][nt][0] + b0; v01.y = acc[mt][nt][1] + b1;
            v23.x = acc[mt][nt][2] + b0; v23.y = acc[mt][nt][3] + b1;
            if (ROUT) {
                v01.x = fmaxf(v01.x, 0.f); v01.y = fmaxf(v01.y, 0.f);
                v23.x = fmaxf(v23.x, 0.f); v23.y = fmaxf(v23.y, 0.f);
            }
            if (row0 < M)     *(float2*)(C + (size_t)row0 * 128 + col) = v01;
            if (row0 + 8 < M) *(float2*)(C + (size_t)(row0 + 8) * 128 + col) = v23;
        }
    }
}

// ---------------------------------------------------------------------------
// GCN aggregation (gather, no atomics): one warp per dst node.
// ---------------------------------------------------------------------------
__global__ __launch_bounds__(256)
void aggregate_kernel(int xwOff, const float* __restrict__ bias,
                      int outOff, int n) {
    const float4* xw4 = (const float4*)(g_scratch + xwOff);
    float4* out4 = (float4*)(g_scratch + outOff);
    int d = (blockIdx.x * blockDim.x + threadIdx.x) >> 5;
    int lane = threadIdx.x & 31;
    if (d >= n) return;

    float di = g_dis[d];
    float sn = di * di;
    float4 b = ((const float4*)bias)[lane];
    float4 x = xw4[(size_t)d * 32 + lane];
    float4 acc;
    acc.x = b.x + sn * x.x; acc.y = b.y + sn * x.y;
    acc.z = b.z + sn * x.z; acc.w = b.w + sn * x.w;

    int i = g_rowptr[d];
    const int end = g_rowptr[d + 1];
    for (; i + 1 < end; i += 2) {
        int s0 = g_csr_src[i], s1 = g_csr_src[i + 1];
        float n0 = g_csr_norm[i], n1 = g_csr_norm[i + 1];
        float4 v0 = xw4[(size_t)s0 * 32 + lane];
        float4 v1 = xw4[(size_t)s1 * 32 + lane];
        acc.x += n0 * v0.x + n1 * v1.x;
        acc.y += n0 * v0.y + n1 * v1.y;
        acc.z += n0 * v0.z + n1 * v1.z;
        acc.w += n0 * v0.w + n1 * v1.w;
    }
    if (i < end) {
        int s0 = g_csr_src[i];
        float n0 = g_csr_norm[i];
        float4 v0 = xw4[(size_t)s0 * 32 + lane];
        acc.x += n0 * v0.x; acc.y += n0 * v0.y;
        acc.z += n0 * v0.z; acc.w += n0 * v0.w;
    }
    out4[(size_t)d * 32 + lane] = acc;
}

// ---------------------------------------------------------------------------
// Edge classifier: out[e] = sigmoid( dot(relu(A[src]+B[dst]), w2) + b2 )
// ---------------------------------------------------------------------------
__global__ void edge_cls_kernel(const int* __restrict__ ei,
                                int aOff, int bOff,
                                const float* __restrict__ w2,
                                const float* __restrict__ b2,
                                float* __restrict__ out, int E) {
    const float* Amat = g_scratch + aOff;
    const float* Bmat = g_scratch + bOff;
    int w = (blockIdx.x * blockDim.x + threadIdx.x) >> 5;
    int lane = threadIdx.x & 31;
    if (w >= E) return;
    int s = ei[w];
    int d = ei[(size_t)E + w];
    float4 a = ((const float4*)(Amat + (size_t)s * H))[lane];
    float4 b = ((const float4*)(Bmat + (size_t)d * H))[lane];
    float4 ww = ((const float4*)w2)[lane];
    float p = fmaxf(a.x + b.x, 0.f) * ww.x
            + fmaxf(a.y + b.y, 0.f) * ww.y
            + fmaxf(a.z + b.z, 0.f) * ww.z
            + fmaxf(a.w + b.w, 0.f) * ww.w;
#pragma unroll
    for (int off = 16; off; off >>= 1)
        p += __shfl_xor_sync(0xffffffffu, p, off);
    if (lane == 0) {
        float z = p + b2[0];
        out[w] = 1.0f / (1.0f + __expf(-z));
    }
}

// ---------------------------------------------------------------------------
extern "C" void kernel_launch(void* const* d_in, const int* in_sizes, int n_in,
                              void* d_out, int out_size) {
    const float* nf      = (const float*)d_in[0];
    const int*   ei      = (const int*)d_in[1];
    const float* enc_w1  = (const float*)d_in[2];
    const float* enc_b1  = (const float*)d_in[3];
    const float* enc_w2  = (const float*)d_in[4];
    const float* enc_b2  = (const float*)d_in[5];
    const float* conv_w1 = (const float*)d_in[6];
    const float* conv_b1 = (const float*)d_in[7];
    const float* conv_w2 = (const float*)d_in[8];
    const float* conv_b2 = (const float*)d_in[9];
    const float* conv_w3 = (const float*)d_in[10];
    const float* conv_b3 = (const float*)d_in[11];
    const float* cls_w1  = (const float*)d_in[12];
    const float* cls_b1  = (const float*)d_in[13];
    const float* cls_w2  = (const float*)d_in[14];
    const float* cls_b2  = (const float*)d_in[15];

    const int n = in_sizes[0] / FDIM;
    const int E = in_sizes[1] / 2;

    const int T = 256;
    const int gm = (n + 127) / 128;
    const int gN = (n + T - 1) / T;
    const int gE = (E + T - 1) / T;
    const int gAgg = (n * 32 + T - 1) / T;
    const int nb = (n + 1023) / 1024;
    const long long eThreads = (long long)E * 32;
    const int gEdge = (int)((eThreads + T - 1) / T);

    // CSR build + normalization
    zero_int_kernel<<<gN, T>>>(n);
    count_kernel<<<gE, T>>>(ei, E);
    dis_kernel<<<gN, T>>>(n);
    scan_phase1<<<nb, 256>>>(n);
    scan_phase2<<<1, 64>>>(nb);
    scan_phase3<<<nb, 256>>>(n, E);
    fill_kernel<<<gE, T>>>(ei, E);

    // node encoder: buf1 = relu(nf@W1+b1e)@W2 + b2e
    gemm_tf32<false, true, true><<<gm, 256>>>(nf, 0, enc_w1, enc_b1, BUF0_OFF, n, FDIM);
    gemm_tf32<false, false, true><<<gm, 256>>>(nullptr, BUF0_OFF, enc_w2, enc_b2, BUF1_OFF, n, H);

    // conv1 (relu deferred to next GEMM input)
    gemm_tf32<false, false, false><<<gm, 256>>>(nullptr, BUF1_OFF, conv_w1, nullptr, BUF0_OFF, n, H);
    aggregate_kernel<<<gAgg, T>>>(BUF0_OFF, conv_b1, BUF2_OFF, n);

    // conv2
    gemm_tf32<true, false, false><<<gm, 256>>>(nullptr, BUF2_OFF, conv_w2, nullptr, BUF0_OFF, n, H);
    aggregate_kernel<<<gAgg, T>>>(BUF0_OFF, conv_b2, BUF1_OFF, n);

    // conv3
    gemm_tf32<true, false, false><<<gm, 256>>>(nullptr, BUF1_OFF, conv_w3, nullptr, BUF0_OFF, n, H);
    aggregate_kernel<<<gAgg, T>>>(BUF0_OFF, conv_b3, BUF2_OFF, n);

    // classifier partials: A = X@W1_top + cls_b1 (buf0), B = X@W1_bot (buf1)
    gemm_tf32<false, false, true><<<gm, 256>>>(nullptr, BUF2_OFF, cls_w1, cls_b1, BUF0_OFF, n, H);
    gemm_tf32<false, false, false><<<gm, 256>>>(nullptr, BUF2_OFF, cls_w1 + 128 * 128, nullptr, BUF1_OFF, n, H);

    // per-edge score
    edge_cls_kernel<<<gEdge, T>>>(ei, BUF0_OFF, BUF1_OFF, cls_w2, cls_b2, (float*)d_out, E);
}

// round 9
// speedup vs baseline: 1.3445x; 1.3445x over previous
#include <cuda_runtime.h>
#include <math.h>

#define FDIM 256
#define H 128
#define NMAX 50000
#define EMAX 1600000

// Scratch (allocation-free rule: __device__ globals)
#define BUF0_OFF 0
#define BUF1_OFF (NMAX * H)
#define BUF2_OFF (2 * NMAX * H)
__device__ float g_scratch[3 * NMAX * H];
__device__ float g_dis[NMAX];
__device__ int   g_cnt[NMAX];
__device__ int   g_fill[NMAX];
__device__ int   g_rowptr[NMAX + 1];
__device__ int   g_csr_src[EMAX];
__device__ float g_csr_norm[EMAX];
__device__ int   g_blocksum[64];
__device__ int   g_blockoff[64];

__device__ __forceinline__ const float* rsv(const float* p, int off) {
    return p ? p : (g_scratch + off);
}

// ---------------------------------------------------------------------------
// CSR build: count -> dis -> 3-phase scan -> fill
// ---------------------------------------------------------------------------
__global__ void zero_int_kernel(int n) {
    int i = blockIdx.x * blockDim.x + threadIdx.x;
    if (i < n) { g_cnt[i] = 0; g_fill[i] = 0; }
}

__global__ void count_kernel(const int* __restrict__ ei, int E) {
    int e = blockIdx.x * blockDim.x + threadIdx.x;
    if (e < E) atomicAdd(&g_cnt[ei[(size_t)E + e]], 1);
}

__global__ void dis_kernel(int n) {
    int i = blockIdx.x * blockDim.x + threadIdx.x;
    if (i < n) g_dis[i] = rsqrtf((float)(g_cnt[i] + 1));  // +1 self loop
}

__global__ void scan_phase1(int n) {
    int t = threadIdx.x;
    int base = blockIdx.x * 1024 + t * 4;
    int s = 0;
#pragma unroll
    for (int j = 0; j < 4; j++) { int i = base + j; if (i < n) s += g_cnt[i]; }
#pragma unroll
    for (int off = 16; off; off >>= 1) s += __shfl_xor_sync(0xffffffffu, s, off);
    __shared__ int wsum[8];
    if ((t & 31) == 0) wsum[t >> 5] = s;
    __syncthreads();
    if (t == 0) {
        int tot = 0;
#pragma unroll
        for (int w = 0; w < 8; w++) tot += wsum[w];
        g_blocksum[blockIdx.x] = tot;
    }
}

__global__ void scan_phase2(int nb) {
    __shared__ int sh[64];
    int t = threadIdx.x;
    int v = (t < nb) ? g_blocksum[t] : 0;
    sh[t] = v;
    __syncthreads();
    for (int off = 1; off < 64; off <<= 1) {
        int tmp = (t >= off) ? sh[t - off] : 0;
        __syncthreads();
        sh[t] += tmp;
        __syncthreads();
    }
    if (t < nb) g_blockoff[t] = sh[t] - v;  // exclusive
}

__global__ void scan_phase3(int n, int E) {
    int t = threadIdx.x;
    int base = blockIdx.x * 1024 + t * 4;
    int v[4]; int s = 0;
#pragma unroll
    for (int j = 0; j < 4; j++) { int i = base + j; v[j] = (i < n) ? g_cnt[i] : 0; s += v[j]; }
    int incl = s;
#pragma unroll
    for (int off = 1; off < 32; off <<= 1) {
        int tmp = __shfl_up_sync(0xffffffffu, incl, off);
        if ((t & 31) >= off) incl += tmp;
    }
    __shared__ int wtot[8];
    __shared__ int woff[8];
    if ((t & 31) == 31) wtot[t >> 5] = incl;
    __syncthreads();
    if (t < 8) {
        int wv = wtot[t];
        int wincl = wv;
#pragma unroll
        for (int off = 1; off < 8; off <<= 1) {
            int tmp = __shfl_up_sync(0x000000ffu, wincl, off);
            if (t >= off) wincl += tmp;
        }
        woff[t] = wincl - wv;
    }
    __syncthreads();
    int prefix = g_blockoff[blockIdx.x] + woff[t >> 5] + (incl - s);
#pragma unroll
    for (int j = 0; j < 4; j++) {
        int i = base + j;
        if (i < n) g_rowptr[i] = prefix;
        prefix += v[j];
    }
    if (blockIdx.x == 0 && t == 0) g_rowptr[n] = E;
}

__global__ void fill_kernel(const int* __restrict__ ei, int E) {
    int e = blockIdx.x * blockDim.x + threadIdx.x;
    if (e >= E) return;
    int s = ei[e];
    int d = ei[(size_t)E + e];
    int pos = g_rowptr[d] + atomicAdd(&g_fill[d], 1);
    g_csr_src[pos] = s;
    g_csr_norm[pos] = g_dis[s] * g_dis[d];
}

// ---------------------------------------------------------------------------
// SGEMM with packed fp32x2 FMA (FFMA2). N fixed to 128, BK=8, 256 threads,
// 8x8 per-thread tile held as 8x4 packed f32x2 accumulators.
// ---------------------------------------------------------------------------
__device__ __forceinline__ unsigned long long bcast2(float f) {
    unsigned long long r;
    unsigned b = __float_as_uint(f);
    asm("mov.b64 %0, {%1, %1};" : "=l"(r) : "r"(b));
    return r;
}

template <bool RIN, bool ROUT, bool BIAS>
__global__ __launch_bounds__(256)
void sgemm_n128(const float* __restrict__ Aext, int aOff,
                const float* __restrict__ W,
                const float* __restrict__ bias,
                int cOff, int M, int K) {
    const float* A = rsv(Aext, aOff);
    float* C = g_scratch + cOff;

    __shared__ float As[2][8][128];
    __shared__ float Bs[2][8][128];

    const int tid = threadIdx.x;
    const int rowBase = blockIdx.x * 128;

    const int innerRowA = tid >> 1;
    const int innerColA = (tid & 1) * 4;
    const int innerRowB = tid >> 5;
    const int innerColB = (tid & 31) * 4;

    const int tr = tid >> 4;
    const int tc = tid & 15;

    unsigned long long acc2[8][4];
#pragma unroll
    for (int i = 0; i < 8; i++)
#pragma unroll
        for (int j = 0; j < 4; j++) acc2[i][j] = 0ull;

    const int mA = rowBase + innerRowA;
    const bool validA = (mA < M);
    const float* Aptr = A + (size_t)mA * K;

    // prologue: load k-tile 0 into buffer 0
    {
        float4 av = make_float4(0.f, 0.f, 0.f, 0.f);
        if (validA) av = *(const float4*)(Aptr + innerColA);
        if (RIN) {
            av.x = fmaxf(av.x, 0.f); av.y = fmaxf(av.y, 0.f);
            av.z = fmaxf(av.z, 0.f); av.w = fmaxf(av.w, 0.f);
        }
        As[0][innerColA + 0][innerRowA] = av.x;
        As[0][innerColA + 1][innerRowA] = av.y;
        As[0][innerColA + 2][innerRowA] = av.z;
        As[0][innerColA + 3][innerRowA] = av.w;
        float4 bv = *(const float4*)(W + (size_t)innerRowB * 128 + innerColB);
        *(float4*)&Bs[0][innerRowB][innerColB] = bv;
    }
    __syncthreads();

    const int nIter = K >> 3;
    for (int it = 0; it < nIter; it++) {
        const int cur = it & 1;
        const bool has = (it + 1 < nIter);
        float4 avn = make_float4(0.f, 0.f, 0.f, 0.f);
        float4 bvn;
        if (has) {
            const int k0 = (it + 1) << 3;
            if (validA) avn = *(const float4*)(Aptr + k0 + innerColA);
            if (RIN) {
                avn.x = fmaxf(avn.x, 0.f); avn.y = fmaxf(avn.y, 0.f);
                avn.z = fmaxf(avn.z, 0.f); avn.w = fmaxf(avn.w, 0.f);
            }
            bvn = *(const float4*)(W + (size_t)(k0 + innerRowB) * 128 + innerColB);
        }

#pragma unroll
        for (int k = 0; k < 8; k++) {
            // B pairs: 8 consecutive floats = 4 packed f32x2 (natural 64-bit lanes)
            ulonglong2 b01 = *(const ulonglong2*)&Bs[cur][k][tc * 8];
            ulonglong2 b23 = *(const ulonglong2*)&Bs[cur][k][tc * 8 + 4];
            unsigned long long rnp[4] = {b01.x, b01.y, b23.x, b23.y};
            // A broadcasts
            float4 a03 = *(const float4*)&As[cur][k][tr * 8];
            float4 a47 = *(const float4*)&As[cur][k][tr * 8 + 4];
            unsigned long long rmp[8];
            rmp[0] = bcast2(a03.x); rmp[1] = bcast2(a03.y);
            rmp[2] = bcast2(a03.z); rmp[3] = bcast2(a03.w);
            rmp[4] = bcast2(a47.x); rmp[5] = bcast2(a47.y);
            rmp[6] = bcast2(a47.z); rmp[7] = bcast2(a47.w);
#pragma unroll
            for (int i = 0; i < 8; i++)
#pragma unroll
                for (int j = 0; j < 4; j++)
                    asm("fma.rn.f32x2 %0, %1, %2, %0;"
                        : "+l"(acc2[i][j]) : "l"(rmp[i]), "l"(rnp[j]));
        }

        if (has) {
            const int nxt = cur ^ 1;
            As[nxt][innerColA + 0][innerRowA] = avn.x;
            As[nxt][innerColA + 1][innerRowA] = avn.y;
            As[nxt][innerColA + 2][innerRowA] = avn.z;
            As[nxt][innerColA + 3][innerRowA] = avn.w;
            *(float4*)&Bs[nxt][innerRowB][innerColB] = bvn;
        }
        __syncthreads();
    }

#pragma unroll
    for (int i = 0; i < 8; i++) {
        int row = rowBase + tr * 8 + i;
        if (row >= M) continue;
        float2 p0 = *(float2*)&acc2[i][0];
        float2 p1 = *(float2*)&acc2[i][1];
        float2 p2 = *(float2*)&acc2[i][2];
        float2 p3 = *(float2*)&acc2[i][3];
        float4 v0 = make_float4(p0.x, p0.y, p1.x, p1.y);
        float4 v1 = make_float4(p2.x, p2.y, p3.x, p3.y);
        int col = tc * 8;
        if (BIAS) {
            v0.x += bias[col + 0]; v0.y += bias[col + 1];
            v0.z += bias[col + 2]; v0.w += bias[col + 3];
            v1.x += bias[col + 4]; v1.y += bias[col + 5];
            v1.z += bias[col + 6]; v1.w += bias[col + 7];
        }
        if (ROUT) {
            v0.x = fmaxf(v0.x, 0.f); v0.y = fmaxf(v0.y, 0.f);
            v0.z = fmaxf(v0.z, 0.f); v0.w = fmaxf(v0.w, 0.f);
            v1.x = fmaxf(v1.x, 0.f); v1.y = fmaxf(v1.y, 0.f);
            v1.z = fmaxf(v1.z, 0.f); v1.w = fmaxf(v1.w, 0.f);
        }
        *(float4*)(C + (size_t)row * 128 + col) = v0;
        *(float4*)(C + (size_t)row * 128 + col + 4) = v1;
    }
}

// ---------------------------------------------------------------------------
// GCN aggregation (gather, no atomics): one warp per dst node.
// ---------------------------------------------------------------------------
__global__ __launch_bounds__(256)
void aggregate_kernel(int xwOff, const float* __restrict__ bias,
                      int outOff, int n) {
    const float4* xw4 = (const float4*)(g_scratch + xwOff);
    float4* out4 = (float4*)(g_scratch + outOff);
    int d = (blockIdx.x * blockDim.x + threadIdx.x) >> 5;
    int lane = threadIdx.x & 31;
    if (d >= n) return;

    float di = g_dis[d];
    float sn = di * di;
    float4 b = ((const float4*)bias)[lane];
    float4 x = xw4[(size_t)d * 32 + lane];
    float4 acc;
    acc.x = b.x + sn * x.x; acc.y = b.y + sn * x.y;
    acc.z = b.z + sn * x.z; acc.w = b.w + sn * x.w;

    int i = g_rowptr[d];
    const int end = g_rowptr[d + 1];
    for (; i + 1 < end; i += 2) {
        int s0 = g_csr_src[i], s1 = g_csr_src[i + 1];
        float n0 = g_csr_norm[i], n1 = g_csr_norm[i + 1];
        float4 v0 = xw4[(size_t)s0 * 32 + lane];
        float4 v1 = xw4[(size_t)s1 * 32 + lane];
        acc.x += n0 * v0.x + n1 * v1.x;
        acc.y += n0 * v0.y + n1 * v1.y;
        acc.z += n0 * v0.z + n1 * v1.z;
        acc.w += n0 * v0.w + n1 * v1.w;
    }
    if (i < end) {
        int s0 = g_csr_src[i];
        float n0 = g_csr_norm[i];
        float4 v0 = xw4[(size_t)s0 * 32 + lane];
        acc.x += n0 * v0.x; acc.y += n0 * v0.y;
        acc.z += n0 * v0.z; acc.w += n0 * v0.w;
    }
    out4[(size_t)d * 32 + lane] = acc;
}

// ---------------------------------------------------------------------------
// Edge classifier: out[e] = sigmoid( dot(relu(A[src]+B[dst]), w2) + b2 )
// ---------------------------------------------------------------------------
__global__ void edge_cls_kernel(const int* __restrict__ ei,
                                int aOff, int bOff,
                                const float* __restrict__ w2,
                                const float* __restrict__ b2,
                                float* __restrict__ out, int E) {
    const float* Amat = g_scratch + aOff;
    const float* Bmat = g_scratch + bOff;
    int w = (blockIdx.x * blockDim.x + threadIdx.x) >> 5;
    int lane = threadIdx.x & 31;
    if (w >= E) return;
    int s = ei[w];
    int d = ei[(size_t)E + w];
    float4 a = ((const float4*)(Amat + (size_t)s * H))[lane];
    float4 b = ((const float4*)(Bmat + (size_t)d * H))[lane];
    float4 ww = ((const float4*)w2)[lane];
    float p = fmaxf(a.x + b.x, 0.f) * ww.x
            + fmaxf(a.y + b.y, 0.f) * ww.y
            + fmaxf(a.z + b.z, 0.f) * ww.z
            + fmaxf(a.w + b.w, 0.f) * ww.w;
#pragma unroll
    for (int off = 16; off; off >>= 1)
        p += __shfl_xor_sync(0xffffffffu, p, off);
    if (lane == 0) {
        float z = p + b2[0];
        out[w] = 1.0f / (1.0f + __expf(-z));
    }
}

// ---------------------------------------------------------------------------
extern "C" void kernel_launch(void* const* d_in, const int* in_sizes, int n_in,
                              void* d_out, int out_size) {
    const float* nf      = (const float*)d_in[0];
    const int*   ei      = (const int*)d_in[1];
    const float* enc_w1  = (const float*)d_in[2];
    const float* enc_b1  = (const float*)d_in[3];
    const float* enc_w2  = (const float*)d_in[4];
    const float* enc_b2  = (const float*)d_in[5];
    const float* conv_w1 = (const float*)d_in[6];
    const float* conv_b1 = (const float*)d_in[7];
    const float* conv_w2 = (const float*)d_in[8];
    const float* conv_b2 = (const float*)d_in[9];
    const float* conv_w3 = (const float*)d_in[10];
    const float* conv_b3 = (const float*)d_in[11];
    const float* cls_w1  = (const float*)d_in[12];
    const float* cls_b1  = (const float*)d_in[13];
    const float* cls_w2  = (const float*)d_in[14];
    const float* cls_b2  = (const float*)d_in[15];

    const int n = in_sizes[0] / FDIM;
    const int E = in_sizes[1] / 2;

    const int T = 256;
    const int gm = (n + 127) / 128;
    const int gN = (n + T - 1) / T;
    const int gE = (E + T - 1) / T;
    const int gAgg = (n * 32 + T - 1) / T;
    const int nb = (n + 1023) / 1024;
    const long long eThreads = (long long)E * 32;
    const int gEdge = (int)((eThreads + T - 1) / T);

    // CSR build + normalization
    zero_int_kernel<<<gN, T>>>(n);
    count_kernel<<<gE, T>>>(ei, E);
    dis_kernel<<<gN, T>>>(n);
    scan_phase1<<<nb, 256>>>(n);
    scan_phase2<<<1, 64>>>(nb);
    scan_phase3<<<nb, 256>>>(n, E);
    fill_kernel<<<gE, T>>>(ei, E);

    // node encoder: buf1 = relu(nf@W1+b1e)@W2 + b2e
    sgemm_n128<false, true, true><<<gm, 256>>>(nf, 0, enc_w1, enc_b1, BUF0_OFF, n, FDIM);
    sgemm_n128<false, false, true><<<gm, 256>>>(nullptr, BUF0_OFF, enc_w2, enc_b2, BUF1_OFF, n, H);

    // conv1 (relu deferred to next GEMM input)
    sgemm_n128<false, false, false><<<gm, 256>>>(nullptr, BUF1_OFF, conv_w1, nullptr, BUF0_OFF, n, H);
    aggregate_kernel<<<gAgg, T>>>(BUF0_OFF, conv_b1, BUF2_OFF, n);

    // conv2
    sgemm_n128<true, false, false><<<gm, 256>>>(nullptr, BUF2_OFF, conv_w2, nullptr, BUF0_OFF, n, H);
    aggregate_kernel<<<gAgg, T>>>(BUF0_OFF, conv_b2, BUF1_OFF, n);

    // conv3
    sgemm_n128<true, false, false><<<gm, 256>>>(nullptr, BUF1_OFF, conv_w3, nullptr, BUF0_OFF, n, H);
    aggregate_kernel<<<gAgg, T>>>(BUF0_OFF, conv_b3, BUF2_OFF, n);

    // classifier partials: A = X@W1_top + cls_b1 (buf0), B = X@W1_bot (buf1)
    sgemm_n128<false, false, true><<<gm, 256>>>(nullptr, BUF2_OFF, cls_w1, cls_b1, BUF0_OFF, n, H);
    sgemm_n128<false, false, false><<<gm, 256>>>(nullptr, BUF2_OFF, cls_w1 + 128 * 128, nullptr, BUF1_OFF, n, H);

    // per-edge score
    edge_cls_kernel<<<gEdge, T>>>(ei, BUF0_OFF, BUF1_OFF, cls_w2, cls_b2, (float*)d_out, E);
}

// round 11
// speedup vs baseline: 2.0262x; 1.5071x over previous
#include <cuda_runtime.h>
#include <cuda_bf16.h>
#include <math.h>
#include <stdint.h>

#define FDIM 256
#define H 128
#define NMAX 50000
#define EMAX 1600000

// Scratch (allocation-free rule: __device__ globals)
#define BUF0_OFF 0
#define BUF1_OFF (NMAX * H)
#define BUF2_OFF (2 * NMAX * H)
__device__ float g_scratch[3 * NMAX * H];
__device__ float g_dis[NMAX];
__device__ int   g_cnt[NMAX];
__device__ int   g_fill[NMAX];
__device__ int   g_rowptr[NMAX + 1];
__device__ int   g_csr_src[EMAX];
__device__ float g_csr_norm[EMAX];
__device__ int   g_blocksum[64];
__device__ int   g_blockoff[64];

__device__ __forceinline__ const float* rsv(const float* p, int off) {
    return p ? p : (g_scratch + off);
}

// ---------------------------------------------------------------------------
// CSR build: count -> dis -> 3-phase scan -> fill
// ---------------------------------------------------------------------------
__global__ void zero_int_kernel(int n) {
    int i = blockIdx.x * blockDim.x + threadIdx.x;
    if (i < n) { g_cnt[i] = 0; g_fill[i] = 0; }
}

__global__ void count_kernel(const int* __restrict__ ei, int E) {
    int e = blockIdx.x * blockDim.x + threadIdx.x;
    if (e < E) atomicAdd(&g_cnt[ei[(size_t)E + e]], 1);
}

__global__ void dis_kernel(int n) {
    int i = blockIdx.x * blockDim.x + threadIdx.x;
    if (i < n) g_dis[i] = rsqrtf((float)(g_cnt[i] + 1));  // +1 self loop
}

__global__ void scan_phase1(int n) {
    int t = threadIdx.x;
    int base = blockIdx.x * 1024 + t * 4;
    int s = 0;
#pragma unroll
    for (int j = 0; j < 4; j++) { int i = base + j; if (i < n) s += g_cnt[i]; }
#pragma unroll
    for (int off = 16; off; off >>= 1) s += __shfl_xor_sync(0xffffffffu, s, off);
    __shared__ int wsum[8];
    if ((t & 31) == 0) wsum[t >> 5] = s;
    __syncthreads();
    if (t == 0) {
        int tot = 0;
#pragma unroll
        for (int w = 0; w < 8; w++) tot += wsum[w];
        g_blocksum[blockIdx.x] = tot;
    }
}

__global__ void scan_phase2(int nb) {
    __shared__ int sh[64];
    int t = threadIdx.x;
    int v = (t < nb) ? g_blocksum[t] : 0;
    sh[t] = v;
    __syncthreads();
    for (int off = 1; off < 64; off <<= 1) {
        int tmp = (t >= off) ? sh[t - off] : 0;
        __syncthreads();
        sh[t] += tmp;
        __syncthreads();
    }
    if (t < nb) g_blockoff[t] = sh[t] - v;  // exclusive
}

__global__ void scan_phase3(int n, int E) {
    int t = threadIdx.x;
    int base = blockIdx.x * 1024 + t * 4;
    int v[4]; int s = 0;
#pragma unroll
    for (int j = 0; j < 4; j++) { int i = base + j; v[j] = (i < n) ? g_cnt[i] : 0; s += v[j]; }
    int incl = s;
#pragma unroll
    for (int off = 1; off < 32; off <<= 1) {
        int tmp = __shfl_up_sync(0xffffffffu, incl, off);
        if ((t & 31) >= off) incl += tmp;
    }
    __shared__ int wtot[8];
    __shared__ int woff[8];
    if ((t & 31) == 31) wtot[t >> 5] = incl;
    __syncthreads();
    if (t < 8) {
        int wv = wtot[t];
        int wincl = wv;
#pragma unroll
        for (int off = 1; off < 8; off <<= 1) {
            int tmp = __shfl_up_sync(0x000000ffu, wincl, off);
            if (t >= off) wincl += tmp;
        }
        woff[t] = wincl - wv;
    }
    __syncthreads();
    int prefix = g_blockoff[blockIdx.x] + woff[t >> 5] + (incl - s);
#pragma unroll
    for (int j = 0; j < 4; j++) {
        int i = base + j;
        if (i < n) g_rowptr[i] = prefix;
        prefix += v[j];
    }
    if (blockIdx.x == 0 && t == 0) g_rowptr[n] = E;
}

__global__ void fill_kernel(const int* __restrict__ ei, int E) {
    int e = blockIdx.x * blockDim.x + threadIdx.x;
    if (e >= E) return;
    int s = ei[e];
    int d = ei[(size_t)E + e];
    int pos = g_rowptr[d] + atomicAdd(&g_fill[d], 1);
    g_csr_src[pos] = s;
    g_csr_norm[pos] = g_dis[s] * g_dis[d];
}

// ---------------------------------------------------------------------------
// bf16 mma.sync GEMM (m16n8k16, fp32 accum). N fixed to 128.
// Block 128x128, BK=32, 256 threads = 8 warps (2m x 4n), warp tile 64x32.
// A,B staged as bf16 rows of 80B stride (conflict-free for ldmatrix).
// ---------------------------------------------------------------------------
#define ASTRIDE 40  // bf16 elements per smem row (80 bytes)

__device__ __forceinline__ unsigned cvt2(float x, float y) {
    __nv_bfloat162 h = __floats2bfloat162_rn(x, y);
    return *reinterpret_cast<unsigned*>(&h);
}

template <bool RIN, bool ROUT, bool BIAS>
__global__ __launch_bounds__(256)
void gemm_bf16(const float* __restrict__ Aext, int aOff,
               const float* __restrict__ W,
               const float* __restrict__ bias,
               int cOff, int M, int K) {
    const float* A = rsv(Aext, aOff);
    float* C = g_scratch + cOff;

    __shared__ __align__(16) __nv_bfloat16 sA[128 * ASTRIDE];
    __shared__ __align__(16) __nv_bfloat16 sB[128 * ASTRIDE];

    const int tid = threadIdx.x;
    const int lane = tid & 31;
    const int wid = tid >> 5;
    const int warp_m = wid >> 2;        // 0..1
    const int warp_n = wid & 3;         // 0..3
    const int g = lane >> 2;            // 0..7
    const int tig = lane & 3;           // 0..3
    const int rowBase = blockIdx.x * 128;

    float acc[4][4][4];
#pragma unroll
    for (int mt = 0; mt < 4; mt++)
#pragma unroll
        for (int nt = 0; nt < 4; nt++)
#pragma unroll
            for (int r = 0; r < 4; r++) acc[mt][nt][r] = 0.0f;

    // staging roles
    const int srow = tid >> 1;          // A row / B n (0..127)
    const int shalf = tid & 1;          // col half (16 elements)
    const int aRow = rowBase + srow;
    const bool aValid = (aRow < M);
    const float* aPtr = A + (size_t)aRow * K + shalf * 16;

    // ldmatrix lane addressing
    const int q = lane >> 3;            // quadrant
    const int lr = lane & 7;
    const int arow_l = lr + 8 * (q & 1);        // row within 16
    const int acolB = (q >> 1) * 16;            // byte offset within kstep (8 bf16)
    const int brow_l = lr + 8 * (q >> 1);       // n within 16 (m2,m3 are n+8)
    const int bcolB = (q & 1) * 16;             // k-half byte offset

    const int nTile = K >> 5;
    for (int kt = 0; kt < nTile; kt++) {
        const int k0 = kt << 5;
        // ---- stage A: thread covers row srow, cols [shalf*16, +16) ----
        {
            float4 v0 = make_float4(0,0,0,0), v1 = v0, v2 = v0, v3 = v0;
            if (aValid) {
                const float4* p = (const float4*)(aPtr + k0);
                v0 = p[0]; v1 = p[1]; v2 = p[2]; v3 = p[3];
                if (RIN) {
                    v0.x=fmaxf(v0.x,0.f); v0.y=fmaxf(v0.y,0.f); v0.z=fmaxf(v0.z,0.f); v0.w=fmaxf(v0.w,0.f);
                    v1.x=fmaxf(v1.x,0.f); v1.y=fmaxf(v1.y,0.f); v1.z=fmaxf(v1.z,0.f); v1.w=fmaxf(v1.w,0.f);
                    v2.x=fmaxf(v2.x,0.f); v2.y=fmaxf(v2.y,0.f); v2.z=fmaxf(v2.z,0.f); v2.w=fmaxf(v2.w,0.f);
                    v3.x=fmaxf(v3.x,0.f); v3.y=fmaxf(v3.y,0.f); v3.z=fmaxf(v3.z,0.f); v3.w=fmaxf(v3.w,0.f);
                }
            }
            uint4 u0, u1;
            u0.x = cvt2(v0.x, v0.y); u0.y = cvt2(v0.z, v0.w);
            u0.z = cvt2(v1.x, v1.y); u0.w = cvt2(v1.z, v1.w);
            u1.x = cvt2(v2.x, v2.y); u1.y = cvt2(v2.z, v2.w);
            u1.z = cvt2(v3.x, v3.y); u1.w = cvt2(v3.z, v3.w);
            uint4* dst = (uint4*)(sA + srow * ASTRIDE + shalf * 16);
            dst[0] = u0; dst[1] = u1;
        }
        // ---- stage B: thread covers n=srow, k in [shalf*16, +16) (transpose W) ----
        {
            const float* wp = W + (size_t)(k0 + shalf * 16) * 128 + srow;
            float w[16];
#pragma unroll
            for (int j = 0; j < 16; j++) w[j] = wp[(size_t)j * 128];
            uint4 u0, u1;
            u0.x = cvt2(w[0], w[1]);   u0.y = cvt2(w[2], w[3]);
            u0.z = cvt2(w[4], w[5]);   u0.w = cvt2(w[6], w[7]);
            u1.x = cvt2(w[8], w[9]);   u1.y = cvt2(w[10], w[11]);
            u1.z = cvt2(w[12], w[13]); u1.w = cvt2(w[14], w[15]);
            uint4* dst = (uint4*)(sB + srow * ASTRIDE + shalf * 16);
            dst[0] = u0; dst[1] = u1;
        }
        __syncthreads();

        // ---- compute: 2 k-steps of 16 ----
#pragma unroll
        for (int ks = 0; ks < 2; ks++) {
            // A fragments: 4 m-tiles
            uint32_t af[4][4];
#pragma unroll
            for (int mt = 0; mt < 4; mt++) {
                const __nv_bfloat16* p = sA + (warp_m * 64 + mt * 16 + arow_l) * ASTRIDE + ks * 16;
                uint32_t addr = (uint32_t)__cvta_generic_to_shared(p) + acolB;
                asm volatile("ldmatrix.sync.aligned.m8n8.x4.shared.b16 {%0,%1,%2,%3}, [%4];"
                             : "=r"(af[mt][0]), "=r"(af[mt][1]), "=r"(af[mt][2]), "=r"(af[mt][3])
                             : "r"(addr));
            }
            // B fragments: 2 n-pairs (each covers two 8-col n-tiles)
            uint32_t bf[4][2];
#pragma unroll
            for (int np = 0; np < 2; np++) {
                const __nv_bfloat16* p = sB + (warp_n * 32 + np * 16 + brow_l) * ASTRIDE + ks * 16;
                uint32_t addr = (uint32_t)__cvta_generic_to_shared(p) + bcolB;
                uint32_t r0, r1, r2, r3;
                asm volatile("ldmatrix.sync.aligned.m8n8.x4.shared.b16 {%0,%1,%2,%3}, [%4];"
                             : "=r"(r0), "=r"(r1), "=r"(r2), "=r"(r3)
                             : "r"(addr));
                bf[np * 2][0] = r0;     bf[np * 2][1] = r1;
                bf[np * 2 + 1][0] = r2; bf[np * 2 + 1][1] = r3;
            }
#pragma unroll
            for (int mt = 0; mt < 4; mt++)
#pragma unroll
                for (int nt = 0; nt < 4; nt++) {
                    asm volatile(
                        "mma.sync.aligned.m16n8k16.row.col.f32.bf16.bf16.f32 "
                        "{%0,%1,%2,%3}, {%4,%5,%6,%7}, {%8,%9}, {%0,%1,%2,%3};"
                        : "+f"(acc[mt][nt][0]), "+f"(acc[mt][nt][1]),
                          "+f"(acc[mt][nt][2]), "+f"(acc[mt][nt][3])
                        : "r"(af[mt][0]), "r"(af[mt][1]), "r"(af[mt][2]), "r"(af[mt][3]),
                          "r"(bf[nt][0]), "r"(bf[nt][1]));
                }
        }
        __syncthreads();
    }

    // ---- epilogue ----
#pragma unroll
    for (int mt = 0; mt < 4; mt++) {
        int row0 = rowBase + warp_m * 64 + mt * 16 + g;
#pragma unroll
        for (int nt = 0; nt < 4; nt++) {
            int col = warp_n * 32 + nt * 8 + tig * 2;
            float b0 = 0.f, b1 = 0.f;
            if (BIAS) { b0 = bias[col]; b1 = bias[col + 1]; }
            float2 v01, v23;
            v01.x = acc[mt][nt][0] + b0; v01.y = acc[mt][nt][1] + b1;
            v23.x = acc[mt][nt][2] + b0; v23.y = acc[mt][nt][3] + b1;
            if (ROUT) {
                v01.x = fmaxf(v01.x, 0.f); v01.y = fmaxf(v01.y, 0.f);
                v23.x = fmaxf(v23.x, 0.f); v23.y = fmaxf(v23.y, 0.f);
            }
            if (row0 < M)     *(float2*)(C + (size_t)row0 * 128 + col) = v01;
            if (row0 + 8 < M) *(float2*)(C + (size_t)(row0 + 8) * 128 + col) = v23;
        }
    }
}

// ---------------------------------------------------------------------------
// GCN aggregation (gather, no atomics): one warp per dst node.
// ---------------------------------------------------------------------------
__global__ __launch_bounds__(256)
void aggregate_kernel(int xwOff, const float* __restrict__ bias,
                      int outOff, int n) {
    const float4* xw4 = (const float4*)(g_scratch + xwOff);
    float4* out4 = (float4*)(g_scratch + outOff);
    int d = (blockIdx.x * blockDim.x + threadIdx.x) >> 5;
    int lane = threadIdx.x & 31;
    if (d >= n) return;

    float di = g_dis[d];
    float sn = di * di;
    float4 b = ((const float4*)bias)[lane];
    float4 x = xw4[(size_t)d * 32 + lane];
    float4 acc;
    acc.x = b.x + sn * x.x; acc.y = b.y + sn * x.y;
    acc.z = b.z + sn * x.z; acc.w = b.w + sn * x.w;

    int i = g_rowptr[d];
    const int end = g_rowptr[d + 1];
    for (; i + 1 < end; i += 2) {
        int s0 = g_csr_src[i], s1 = g_csr_src[i + 1];
        float n0 = g_csr_norm[i], n1 = g_csr_norm[i + 1];
        float4 v0 = xw4[(size_t)s0 * 32 + lane];
        float4 v1 = xw4[(size_t)s1 * 32 + lane];
        acc.x += n0 * v0.x + n1 * v1.x;
        acc.y += n0 * v0.y + n1 * v1.y;
        acc.z += n0 * v0.z + n1 * v1.z;
        acc.w += n0 * v0.w + n1 * v1.w;
    }
    if (i < end) {
        int s0 = g_csr_src[i];
        float n0 = g_csr_norm[i];
        float4 v0 = xw4[(size_t)s0 * 32 + lane];
        acc.x += n0 * v0.x; acc.y += n0 * v0.y;
        acc.z += n0 * v0.z; acc.w += n0 * v0.w;
    }
    out4[(size_t)d * 32 + lane] = acc;
}

// ---------------------------------------------------------------------------
// Edge classifier: out[e] = sigmoid( dot(relu(A[src]+B[dst]), w2) + b2 )
// ---------------------------------------------------------------------------
__global__ void edge_cls_kernel(const int* __restrict__ ei,
                                int aOff, int bOff,
                                const float* __restrict__ w2,
                                const float* __restrict__ b2,
                                float* __restrict__ out, int E) {
    const float* Amat = g_scratch + aOff;
    const float* Bmat = g_scratch + bOff;
    int w = (blockIdx.x * blockDim.x + threadIdx.x) >> 5;
    int lane = threadIdx.x & 31;
    if (w >= E) return;
    int s = ei[w];
    int d = ei[(size_t)E + w];
    float4 a = ((const float4*)(Amat + (size_t)s * H))[lane];
    float4 b = ((const float4*)(Bmat + (size_t)d * H))[lane];
    float4 ww = ((const float4*)w2)[lane];
    float p = fmaxf(a.x + b.x, 0.f) * ww.x
            + fmaxf(a.y + b.y, 0.f) * ww.y
            + fmaxf(a.z + b.z, 0.f) * ww.z
            + fmaxf(a.w + b.w, 0.f) * ww.w;
#pragma unroll
    for (int off = 16; off; off >>= 1)
        p += __shfl_xor_sync(0xffffffffu, p, off);
    if (lane == 0) {
        float z = p + b2[0];
        out[w] = 1.0f / (1.0f + __expf(-z));
    }
}

// ---------------------------------------------------------------------------
extern "C" void kernel_launch(void* const* d_in, const int* in_sizes, int n_in,
                              void* d_out, int out_size) {
    const float* nf      = (const float*)d_in[0];
    const int*   ei      = (const int*)d_in[1];
    const float* enc_w1  = (const float*)d_in[2];
    const float* enc_b1  = (const float*)d_in[3];
    const float* enc_w2  = (const float*)d_in[4];
    const float* enc_b2  = (const float*)d_in[5];
    const float* conv_w1 = (const float*)d_in[6];
    const float* conv_b1 = (const float*)d_in[7];
    const float* conv_w2 = (const float*)d_in[8];
    const float* conv_b2 = (const float*)d_in[9];
    const float* conv_w3 = (const float*)d_in[10];
    const float* conv_b3 = (const float*)d_in[11];
    const float* cls_w1  = (const float*)d_in[12];
    const float* cls_b1  = (const float*)d_in[13];
    const float* cls_w2  = (const float*)d_in[14];
    const float* cls_b2  = (const float*)d_in[15];

    const int n = in_sizes[0] / FDIM;
    const int E = in_sizes[1] / 2;

    const int T = 256;
    const int gm = (n + 127) / 128;
    const int gN = (n + T - 1) / T;
    const int gE = (E + T - 1) / T;
    const int gAgg = (n * 32 + T - 1) / T;
    const int nb = (n + 1023) / 1024;
    const long long eThreads = (long long)E * 32;
    const int gEdge = (int)((eThreads + T - 1) / T);

    // CSR build + normalization
    zero_int_kernel<<<gN, T>>>(n);
    count_kernel<<<gE, T>>>(ei, E);
    dis_kernel<<<gN, T>>>(n);
    scan_phase1<<<nb, 256>>>(n);
    scan_phase2<<<1, 64>>>(nb);
    scan_phase3<<<nb, 256>>>(n, E);
    fill_kernel<<<gE, T>>>(ei, E);

    // node encoder: buf1 = relu(nf@W1+b1e)@W2 + b2e
    gemm_bf16<false, true, true><<<gm, 256>>>(nf, 0, enc_w1, enc_b1, BUF0_OFF, n, FDIM);
    gemm_bf16<false, false, true><<<gm, 256>>>(nullptr, BUF0_OFF, enc_w2, enc_b2, BUF1_OFF, n, H);

    // conv1 (relu deferred to next GEMM input)
    gemm_bf16<false, false, false><<<gm, 256>>>(nullptr, BUF1_OFF, conv_w1, nullptr, BUF0_OFF, n, H);
    aggregate_kernel<<<gAgg, T>>>(BUF0_OFF, conv_b1, BUF2_OFF, n);

    // conv2
    gemm_bf16<true, false, false><<<gm, 256>>>(nullptr, BUF2_OFF, conv_w2, nullptr, BUF0_OFF, n, H);
    aggregate_kernel<<<gAgg, T>>>(BUF0_OFF, conv_b2, BUF1_OFF, n);

    // conv3
    gemm_bf16<true, false, false><<<gm, 256>>>(nullptr, BUF1_OFF, conv_w3, nullptr, BUF0_OFF, n, H);
    aggregate_kernel<<<gAgg, T>>>(BUF0_OFF, conv_b3, BUF2_OFF, n);

    // classifier partials: A = X@W1_top + cls_b1 (buf0), B = X@W1_bot (buf1)
    gemm_bf16<false, false, true><<<gm, 256>>>(nullptr, BUF2_OFF, cls_w1, cls_b1, BUF0_OFF, n, H);
    gemm_bf16<false, false, false><<<gm, 256>>>(nullptr, BUF2_OFF, cls_w1 + 128 * 128, nullptr, BUF1_OFF, n, H);

    // per-edge score
    edge_cls_kernel<<<gEdge, T>>>(ei, BUF0_OFF, BUF1_OFF, cls_w2, cls_b2, (float*)d_out, E);
}